// round 2
// baseline (speedup 1.0000x reference)
#include <cuda_runtime.h>
#include <cuda_bf16.h>
#include <stdint.h>

// Problem constants
#define B_FEAT 128
#define U_UNITS 100000
#define NN_NBH 100
#define K_NBR 500
#define N_RUNS 10
#define N_PAIRS 124750  // K*(K-1)/2
#define TILE 32
#define NTILES 16       // ceil(500/32)
#define NTILE_PAIRS 136 // 16*17/2 lower-tri incl diagonal tiles

// Scratch (device globals; no allocation allowed)
__device__ float  g_Y[N_RUNS][K_NBR][B_FEAT];   // normalized centered features, 2.56 MB
__device__ float2 g_P[N_RUNS][K_NBR];           // gathered positions
__device__ double g_acc[N_RUNS][5];             // Sr, Sd, Srd, Srr, Sdd

struct Choice { int v[N_RUNS]; };

// ---------------------------------------------------------------------------
// Kernel 0: zero accumulators (graph replays must be deterministic)
// ---------------------------------------------------------------------------
__global__ void init_kernel() {
    int t = threadIdx.x;
    if (t < N_RUNS * 5) ((double*)g_acc)[t] = 0.0;
}

// ---------------------------------------------------------------------------
// Kernel 1: gather + center + normalize feature columns; gather positions
// grid (K_NBR, N_RUNS), block 128 (one thread per feature dim)
// ---------------------------------------------------------------------------
__global__ void prep_kernel(const float* __restrict__ feat,
                            const float* __restrict__ pos,
                            const int*   __restrict__ nbh,
                            Choice ch) {
    int u   = blockIdx.x;
    int run = blockIdx.y;
    int f   = threadIdx.x;

    int ind = __ldg(&nbh[ch.v[run] * K_NBR + u]);
    float v = __ldg(&feat[f * U_UNITS + ind]);

    __shared__ float red[B_FEAT];
    red[f] = v;
    __syncthreads();
    #pragma unroll
    for (int s = 64; s > 0; s >>= 1) {
        if (f < s) red[f] += red[f + s];
        __syncthreads();
    }
    float mean = red[0] * (1.0f / B_FEAT);
    __syncthreads();

    float c = v - mean;
    red[f] = c * c;
    __syncthreads();
    #pragma unroll
    for (int s = 64; s > 0; s >>= 1) {
        if (f < s) red[f] += red[f + s];
        __syncthreads();
    }
    float inv = rsqrtf(red[0]);

    g_Y[run][u][f] = c * inv;
    if (f == 0) g_P[run][u] = make_float2(__ldg(&pos[ind * 2]), __ldg(&pos[ind * 2 + 1]));
}

// ---------------------------------------------------------------------------
// Kernel 2: pair sums. grid (NTILE_PAIRS, N_RUNS), block 256.
// Each block handles a 32x32 tile of (i, j) pairs (only i > j contribute).
// Y tiles staged in smem as float4 with row stride 33 (S/16 odd -> LDS.128
// conflict-free).
// ---------------------------------------------------------------------------
__global__ __launch_bounds__(256) void pair_kernel() {
    int run = blockIdx.y;
    int t   = blockIdx.x;

    // map linear lower-tri tile index -> (ti, tj), t = ti*(ti+1)/2 + tj
    int ti = (int)((sqrtf(8.0f * (float)t + 1.0f) - 1.0f) * 0.5f);
    while ((ti + 1) * (ti + 2) / 2 <= t) ti++;
    while (ti * (ti + 1) / 2 > t) ti--;
    int tj = t - ti * (ti + 1) / 2;

    int i0 = ti * TILE, j0 = tj * TILE;

    __shared__ float4 Yi[TILE][33];
    __shared__ float4 Yj[TILE][33];
    __shared__ float2 Pi[TILE], Pj[TILE];
    __shared__ float  wsum[8][5];

    int tid = threadIdx.x;

    // stage tiles (32 float4 = 128 floats per row)
    for (int idx = tid; idx < TILE * 32; idx += 256) {
        int r = idx >> 5, c = idx & 31;
        int gi = i0 + r, gj = j0 + r;
        Yi[r][c] = (gi < K_NBR) ? ((const float4*)g_Y[run][gi])[c] : make_float4(0, 0, 0, 0);
        Yj[r][c] = (gj < K_NBR) ? ((const float4*)g_Y[run][gj])[c] : make_float4(0, 0, 0, 0);
    }
    if (tid < TILE) {
        int gi = i0 + tid;
        Pi[tid] = (gi < K_NBR) ? g_P[run][gi] : make_float2(0, 0);
    } else if (tid < 2 * TILE) {
        int k = tid - TILE, gj = j0 + k;
        Pj[k] = (gj < K_NBR) ? g_P[run][gj] : make_float2(0, 0);
    }
    __syncthreads();

    float sr = 0.f, sd = 0.f, srd = 0.f, srr = 0.f, sdd = 0.f;

    #pragma unroll
    for (int k = 0; k < 4; k++) {
        int p  = tid + k * 256;
        int li = p >> 5, lj = p & 31;
        int gi = i0 + li, gj = j0 + lj;
        if (gi < K_NBR && gj < K_NBR && gi > gj) {
            float dot = 0.f;
            #pragma unroll
            for (int c = 0; c < 32; c++) {
                float4 a = Yi[li][c];
                float4 b = Yj[lj][c];
                dot += a.x * b.x + a.y * b.y + a.z * b.z + a.w * b.w;
            }
            float dx = Pi[li].x - Pj[lj].x;
            float dy = Pi[li].y - Pj[lj].y;
            float ds = 1.0f / (sqrtf(dx * dx + dy * dy) + 1.0f);
            sr  += dot;
            sd  += ds;
            srd += dot * ds;
            srr += dot * dot;
            sdd += ds * ds;
        }
    }

    // warp reduce
    #pragma unroll
    for (int off = 16; off > 0; off >>= 1) {
        sr  += __shfl_down_sync(0xFFFFFFFFu, sr,  off);
        sd  += __shfl_down_sync(0xFFFFFFFFu, sd,  off);
        srd += __shfl_down_sync(0xFFFFFFFFu, srd, off);
        srr += __shfl_down_sync(0xFFFFFFFFu, srr, off);
        sdd += __shfl_down_sync(0xFFFFFFFFu, sdd, off);
    }
    int wid = tid >> 5, lane = tid & 31;
    if (lane == 0) {
        wsum[wid][0] = sr;  wsum[wid][1] = sd;  wsum[wid][2] = srd;
        wsum[wid][3] = srr; wsum[wid][4] = sdd;
    }
    __syncthreads();
    if (tid == 0) {
        double a0 = 0, a1 = 0, a2 = 0, a3 = 0, a4 = 0;
        #pragma unroll
        for (int w = 0; w < 8; w++) {
            a0 += wsum[w][0]; a1 += wsum[w][1]; a2 += wsum[w][2];
            a3 += wsum[w][3]; a4 += wsum[w][4];
        }
        atomicAdd(&g_acc[run][0], a0);
        atomicAdd(&g_acc[run][1], a1);
        atomicAdd(&g_acc[run][2], a2);
        atomicAdd(&g_acc[run][3], a3);
        atomicAdd(&g_acc[run][4], a4);
    }
}

// ---------------------------------------------------------------------------
// Kernel 3: Pearson r per run, mean loss
// ---------------------------------------------------------------------------
__global__ void final_kernel(float* __restrict__ out) {
    __shared__ double losses[N_RUNS];
    int t = threadIdx.x;
    if (t < N_RUNS) {
        double Sr  = g_acc[t][0], Sd  = g_acc[t][1], Srd = g_acc[t][2];
        double Srr = g_acc[t][3], Sdd = g_acc[t][4];
        double P = (double)N_PAIRS;
        double num = Srd - Sr * Sd / P;
        double den = sqrt((Srr - Sr * Sr / P) * (Sdd - Sd * Sd / P));
        double r = num / den;
        losses[t] = (1.0 - r) * 0.5;
    }
    __syncthreads();
    if (t == 0) {
        double s = 0;
        #pragma unroll
        for (int i = 0; i < N_RUNS; i++) s += losses[i];
        out[0] = (float)(s / N_RUNS);
    }
}

// ---------------------------------------------------------------------------
// Host-side JAX threefry2x32 reproduction for choice = randint(key(42),(10,),0,100)
// ---------------------------------------------------------------------------
static inline uint32_t rotl32(uint32_t x, int r) { return (x << r) | (x >> (32 - r)); }

static void threefry2x32(uint32_t k0, uint32_t k1, uint32_t c0, uint32_t c1,
                         uint32_t* o0, uint32_t* o1) {
    uint32_t ks0 = k0, ks1 = k1, ks2 = k0 ^ k1 ^ 0x1BD11BDAu;
    uint32_t x0 = c0 + ks0, x1 = c1 + ks1;
    const int rotA[4] = {13, 15, 26, 6};
    const int rotB[4] = {17, 29, 16, 24};
#define TF_ROUND4(R) do { for (int _i = 0; _i < 4; _i++) { \
        x0 += x1; x1 = rotl32(x1, (R)[_i]); x1 ^= x0; } } while (0)
    TF_ROUND4(rotA); x0 += ks1; x1 += ks2 + 1;
    TF_ROUND4(rotB); x0 += ks2; x1 += ks0 + 2;
    TF_ROUND4(rotA); x0 += ks0; x1 += ks1 + 3;
    TF_ROUND4(rotB); x0 += ks1; x1 += ks2 + 4;
    TF_ROUND4(rotA); x0 += ks2; x1 += ks0 + 5;
#undef TF_ROUND4
    *o0 = x0; *o1 = x1;
}

extern "C" void kernel_launch(void* const* d_in, const int* in_sizes, int n_in,
                              void* d_out, int out_size) {
    const float* feat = (const float*)d_in[0];
    const float* pos  = (const float*)d_in[1];
    const int*   nbh  = (const int*)d_in[2];

    // choice = jax.random.randint(key(42), (10,), 0, 100)
    // random_bits: threefry2x32(key=(0,42), counts split [0..4] | [5..9])
    uint32_t bits[N_RUNS];
    for (uint32_t i = 0; i < 5; i++) {
        uint32_t o0, o1;
        threefry2x32(0u, 42u, i, i + 5u, &o0, &o1);
        bits[i] = o0;
        bits[i + 5] = o1;
    }
    // jax randint bias-correction: mult = (2^16 % 100)^2 % 100 = 96
    Choice ch;
    for (int i = 0; i < N_RUNS; i++) {
        uint32_t b = bits[i];
        uint32_t hi = b >> 16, lo = b & 0xFFFFu;
        ch.v[i] = (int)(((hi % 100u) * 96u + (lo % 100u)) % 100u);
    }

    init_kernel<<<1, 64>>>();
    prep_kernel<<<dim3(K_NBR, N_RUNS), B_FEAT>>>(feat, pos, nbh, ch);
    pair_kernel<<<dim3(NTILE_PAIRS, N_RUNS), 256>>>();
    final_kernel<<<1, 32>>>((float*)d_out);
}

// round 3
// speedup vs baseline: 1.6819x; 1.6819x over previous
#include <cuda_runtime.h>
#include <cuda_bf16.h>
#include <stdint.h>

// Problem constants
#define B_FEAT 128
#define U_UNITS 100000
#define K_NBR 500
#define N_RUNS 10
#define N_PAIRS 124750.0
#define T2 64          // pair tile edge
#define NT2 8          // ceil(500/64)
#define NTP2 36        // 8*9/2 lower-tri tile pairs (incl diagonal)
#define TOTAL_BLOCKS (NTP2 * N_RUNS)

// Scratch (device globals; no allocation allowed)
__device__ float  g_Y[N_RUNS][K_NBR][B_FEAT];   // normalized centered features
__device__ float2 g_P[N_RUNS][K_NBR];           // gathered positions
__device__ double g_part[TOTAL_BLOCKS][5];      // per-block partial sums
__device__ int    g_done = 0;                   // finalize counter (reset by finalizer)

struct Choice { int v[N_RUNS]; };

// ---------------------------------------------------------------------------
// Kernel 1: gather + center + normalize feature columns; gather positions
// grid (K_NBR, N_RUNS), block 128 (one thread per feature dim)
// ---------------------------------------------------------------------------
__global__ void prep_kernel(const float* __restrict__ feat,
                            const float* __restrict__ pos,
                            const int*   __restrict__ nbh,
                            Choice ch) {
    int u   = blockIdx.x;
    int run = blockIdx.y;
    int f   = threadIdx.x;
    int wid = f >> 5, lane = f & 31;

    int ind = __ldg(&nbh[ch.v[run] * K_NBR + u]);
    float v = __ldg(&feat[f * U_UNITS + ind]);

    __shared__ float ws[4];
    // pass 1: sum -> mean
    float s = v;
    #pragma unroll
    for (int o = 16; o > 0; o >>= 1) s += __shfl_xor_sync(0xFFFFFFFFu, s, o);
    if (lane == 0) ws[wid] = s;
    __syncthreads();
    float mean = (ws[0] + ws[1] + ws[2] + ws[3]) * (1.0f / B_FEAT);
    __syncthreads();

    // pass 2: centered sumsq -> inv norm
    float c = v - mean;
    float q = c * c;
    #pragma unroll
    for (int o = 16; o > 0; o >>= 1) q += __shfl_xor_sync(0xFFFFFFFFu, q, o);
    if (lane == 0) ws[wid] = q;
    __syncthreads();
    float inv = rsqrtf(ws[0] + ws[1] + ws[2] + ws[3]);

    g_Y[run][u][f] = c * inv;
    if (f == 0) g_P[run][u] = make_float2(__ldg(&pos[ind * 2]), __ldg(&pos[ind * 2 + 1]));
}

// ---------------------------------------------------------------------------
// Kernel 2: pair sums with 64x64 tiles, 16x16 threads, 4x4 register micro-tile.
// Per c-step: 8 LDS.128 feed 64 FFMA (16 pairs) -> LSU/FMA balanced.
// Last block (fence+counter) reduces all partials, computes the loss, writes
// out, and resets the counter for the next graph replay.
// Dynamic smem: Yi[64][33] + Yj[64][33] float4 (stride 33 -> conflict-free
// LDS.128) + positions = 68608 B.
// ---------------------------------------------------------------------------
__global__ __launch_bounds__(256) void pair_kernel(float* __restrict__ out) {
    extern __shared__ char sraw[];
    float4 (*Yi)[33] = (float4 (*)[33])sraw;
    float4 (*Yj)[33] = (float4 (*)[33])(sraw + T2 * 33 * sizeof(float4));
    float2* Pi = (float2*)(sraw + 2 * T2 * 33 * sizeof(float4));
    float2* Pj = Pi + T2;

    int run = blockIdx.y;
    int t   = blockIdx.x;
    int ti = 0;
    while ((ti + 1) * (ti + 2) / 2 <= t) ti++;
    int tj = t - ti * (ti + 1) / 2;
    int i0 = ti * T2, j0 = tj * T2;

    int tid = threadIdx.x;

    // stage tiles (each row = 32 float4 = 128 floats)
    for (int idx = tid; idx < T2 * 32; idx += 256) {
        int r = idx >> 5, c = idx & 31;
        int gi = i0 + r, gj = j0 + r;
        Yi[r][c] = (gi < K_NBR) ? ((const float4*)g_Y[run][gi])[c] : make_float4(0, 0, 0, 0);
        Yj[r][c] = (gj < K_NBR) ? ((const float4*)g_Y[run][gj])[c] : make_float4(0, 0, 0, 0);
    }
    if (tid < T2) {
        Pi[tid] = (i0 + tid < K_NBR) ? g_P[run][i0 + tid] : make_float2(0, 0);
    } else if (tid < 2 * T2) {
        int k = tid - T2;
        Pj[k] = (j0 + k < K_NBR) ? g_P[run][j0 + k] : make_float2(0, 0);
    }
    __syncthreads();

    int tx = tid & 15, ty = tid >> 4;

    float acc[4][4] = {};
    #pragma unroll 4
    for (int c = 0; c < 32; c++) {
        float4 af[4], bf[4];
        #pragma unroll
        for (int a = 0; a < 4; a++) af[a] = Yi[ty + 16 * a][c];
        #pragma unroll
        for (int b = 0; b < 4; b++) bf[b] = Yj[tx + 16 * b][c];
        #pragma unroll
        for (int a = 0; a < 4; a++)
            #pragma unroll
            for (int b = 0; b < 4; b++)
                acc[a][b] += af[a].x * bf[b].x + af[a].y * bf[b].y
                           + af[a].z * bf[b].z + af[a].w * bf[b].w;
    }

    float sr = 0.f, sd = 0.f, srd = 0.f, srr = 0.f, sdd = 0.f;
    #pragma unroll
    for (int a = 0; a < 4; a++) {
        int li = ty + 16 * a, gi = i0 + li;
        float2 pi = Pi[li];
        #pragma unroll
        for (int b = 0; b < 4; b++) {
            int lj = tx + 16 * b, gj = j0 + lj;
            if (gi < K_NBR && gj < K_NBR && gi > gj) {
                float dot = acc[a][b];
                float dx = pi.x - Pj[lj].x;
                float dy = pi.y - Pj[lj].y;
                float ds = 1.0f / (sqrtf(dx * dx + dy * dy) + 1.0f);
                sr  += dot;
                sd  += ds;
                srd += dot * ds;
                srr += dot * dot;
                sdd += ds * ds;
            }
        }
    }

    // block reduce 5 sums
    #pragma unroll
    for (int off = 16; off > 0; off >>= 1) {
        sr  += __shfl_down_sync(0xFFFFFFFFu, sr,  off);
        sd  += __shfl_down_sync(0xFFFFFFFFu, sd,  off);
        srd += __shfl_down_sync(0xFFFFFFFFu, srd, off);
        srr += __shfl_down_sync(0xFFFFFFFFu, srr, off);
        sdd += __shfl_down_sync(0xFFFFFFFFu, sdd, off);
    }
    __shared__ float wsum[16][5];
    int wid = tid >> 5, lane = tid & 31;
    if (lane == 0) {
        wsum[wid][0] = sr;  wsum[wid][1] = sd;  wsum[wid][2] = srd;
        wsum[wid][3] = srr; wsum[wid][4] = sdd;
    }
    __syncthreads();
    if (tid == 0) {
        double a0 = 0, a1 = 0, a2 = 0, a3 = 0, a4 = 0;
        #pragma unroll
        for (int w = 0; w < 8; w++) {
            a0 += wsum[w][0]; a1 += wsum[w][1]; a2 += wsum[w][2];
            a3 += wsum[w][3]; a4 += wsum[w][4];
        }
        double* p = g_part[run * NTP2 + t];
        p[0] = a0; p[1] = a1; p[2] = a2; p[3] = a3; p[4] = a4;
    }

    // ---- last-block finalize ----
    __shared__ int isLast;
    if (tid == 0) {
        __threadfence();
        int done = atomicAdd(&g_done, 1);
        isLast = (done == TOTAL_BLOCKS - 1) ? 1 : 0;
    }
    __syncthreads();
    if (!isLast) return;

    __shared__ double red[50];
    if (tid < 50) {
        int rn = tid / 5, cp = tid % 5;
        double s = 0;
        #pragma unroll
        for (int b2 = 0; b2 < NTP2; b2++) s += g_part[rn * NTP2 + b2][cp];
        red[tid] = s;
    }
    __syncthreads();
    __shared__ double lsum[N_RUNS];
    if (tid < N_RUNS) {
        double Sr  = red[tid * 5 + 0], Sd  = red[tid * 5 + 1], Srd = red[tid * 5 + 2];
        double Srr = red[tid * 5 + 3], Sdd = red[tid * 5 + 4];
        double num = Srd - Sr * Sd / N_PAIRS;
        double den = sqrt((Srr - Sr * Sr / N_PAIRS) * (Sdd - Sd * Sd / N_PAIRS));
        lsum[tid] = (1.0 - num / den) * 0.5;
    }
    __syncthreads();
    if (tid == 0) {
        double s = 0;
        #pragma unroll
        for (int i = 0; i < N_RUNS; i++) s += lsum[i];
        out[0] = (float)(s / N_RUNS);
        g_done = 0;  // reset for next graph replay
    }
}

// ---------------------------------------------------------------------------
// Host-side JAX threefry2x32 reproduction for choice = randint(key(42),(10,),0,100)
// ---------------------------------------------------------------------------
static inline uint32_t rotl32(uint32_t x, int r) { return (x << r) | (x >> (32 - r)); }

static void threefry2x32(uint32_t k0, uint32_t k1, uint32_t c0, uint32_t c1,
                         uint32_t* o0, uint32_t* o1) {
    uint32_t ks0 = k0, ks1 = k1, ks2 = k0 ^ k1 ^ 0x1BD11BDAu;
    uint32_t x0 = c0 + ks0, x1 = c1 + ks1;
    const int rotA[4] = {13, 15, 26, 6};
    const int rotB[4] = {17, 29, 16, 24};
#define TF_ROUND4(R) do { for (int _i = 0; _i < 4; _i++) { \
        x0 += x1; x1 = rotl32(x1, (R)[_i]); x1 ^= x0; } } while (0)
    TF_ROUND4(rotA); x0 += ks1; x1 += ks2 + 1;
    TF_ROUND4(rotB); x0 += ks2; x1 += ks0 + 2;
    TF_ROUND4(rotA); x0 += ks0; x1 += ks1 + 3;
    TF_ROUND4(rotB); x0 += ks1; x1 += ks2 + 4;
    TF_ROUND4(rotA); x0 += ks2; x1 += ks0 + 5;
#undef TF_ROUND4
    *o0 = x0; *o1 = x1;
}

extern "C" void kernel_launch(void* const* d_in, const int* in_sizes, int n_in,
                              void* d_out, int out_size) {
    const float* feat = (const float*)d_in[0];
    const float* pos  = (const float*)d_in[1];
    const int*   nbh  = (const int*)d_in[2];

    uint32_t bits[N_RUNS];
    for (uint32_t i = 0; i < 5; i++) {
        uint32_t o0, o1;
        threefry2x32(0u, 42u, i, i + 5u, &o0, &o1);
        bits[i] = o0;
        bits[i + 5] = o1;
    }
    Choice ch;
    for (int i = 0; i < N_RUNS; i++) {
        uint32_t b = bits[i];
        uint32_t hi = b >> 16, lo = b & 0xFFFFu;
        ch.v[i] = (int)(((hi % 100u) * 96u + (lo % 100u)) % 100u);
    }

    const int SMEM = 2 * T2 * 33 * (int)sizeof(float4) + 2 * T2 * (int)sizeof(float2);
    cudaFuncSetAttribute(pair_kernel, cudaFuncAttributeMaxDynamicSharedMemorySize, SMEM);

    prep_kernel<<<dim3(K_NBR, N_RUNS), B_FEAT>>>(feat, pos, nbh, ch);
    pair_kernel<<<dim3(NTP2, N_RUNS), 256, SMEM>>>((float*)d_out);
}